// round 1
// baseline (speedup 1.0000x reference)
#include <cuda_runtime.h>
#include <cstddef>
#include <cstdint>

#define Bsz   1024
#define DF    2048
#define DIM   128
#define CC    8192
#define PP    8
#define NNq   4
#define NC    (NNq * CC)            // 32768
#define PC    (PP * CC)             // 65536
#define SIMW  (Bsz + PP + NNq * (CC - 1))  // 33796

static constexpr size_t OFF_SIM  = 0;
static constexpr size_t OFF_LAB  = (size_t)Bsz * SIMW;
static constexpr size_t OFF_LQ   = OFF_LAB + (size_t)Bsz * SIMW;
static constexpr size_t OFF_LK   = OFF_LQ + (size_t)Bsz * CC;
static constexpr size_t OFF_NQ2  = OFF_LK + (size_t)Bsz * CC;
static constexpr size_t OFF_PQ2  = OFF_NQ2 + (size_t)DIM * NC;
static constexpr size_t OFF_NPTR = OFF_PQ2 + (size_t)DIM * PC;
static constexpr size_t OFF_PPTR = OFF_NPTR + CC;

// ---------------- device scratch (no allocations allowed) ----------------
__device__ float g_Hq[(size_t)Bsz * DF];
__device__ float g_Hk[(size_t)Bsz * DF];
__device__ float g_scq[DF], g_shq[DF], g_sck[DF], g_shk[DF];
__device__ float g_featq[(size_t)Bsz * DIM];
__device__ float g_featk[(size_t)Bsz * DIM];
__device__ int   g_rank[Bsz];
__device__ int   g_cntb[Bsz];

// ---------------- SGEMM: 128x128 tile, BK=16, 8x8/thread, 256 threads ----
// MODE 0: C = A@B (+bias)
// MODE 2: A' = relu(A*scale + shift) applied on load, C = A'@B (+bias)
// MODE 3: B is transposed (B[k][n] = Bm[n*ldb + k]), no bias
// MODE 4: neg epilogue: scatter-write skipping the label's NNq columns
template <int MODE>
__global__ __launch_bounds__(256) void sgemm_k(
    const float* __restrict__ A, const float* __restrict__ Bm,
    const float* __restrict__ bias, float* __restrict__ Cc,
    int K, int lda, int ldb, int ldc,
    const float* __restrict__ scale, const float* __restrict__ shift,
    const int* __restrict__ labels)
{
    __shared__ float As[16][128];
    __shared__ float Bs[16][128];
    const int tid   = threadIdx.x;
    const int mBase = blockIdx.y * 128;
    const int nBase = blockIdx.x * 128;
    const int tx = tid & 15;         // 16 threads across N
    const int ty = tid >> 4;         // 16 threads across M
    const int aRow = tid >> 2;       // 0..63
    const int aCol = (tid & 3) << 2; // 0,4,8,12
    const int bRow = tid >> 5;       // 0..7
    const int bCol = (tid & 31) << 2;

    float acc[8][8] = {};

    for (int k0 = 0; k0 < K; k0 += 16) {
        #pragma unroll
        for (int p = 0; p < 2; ++p) {
            int r = aRow + p * 64;
            float4 v = *(const float4*)(A + (size_t)(mBase + r) * lda + k0 + aCol);
            if (MODE == 2) {
                float4 sc = *(const float4*)(scale + k0 + aCol);
                float4 sh = *(const float4*)(shift + k0 + aCol);
                v.x = fmaxf(fmaf(v.x, sc.x, sh.x), 0.f);
                v.y = fmaxf(fmaf(v.y, sc.y, sh.y), 0.f);
                v.z = fmaxf(fmaf(v.z, sc.z, sh.z), 0.f);
                v.w = fmaxf(fmaf(v.w, sc.w, sh.w), 0.f);
            }
            As[aCol + 0][r] = v.x; As[aCol + 1][r] = v.y;
            As[aCol + 2][r] = v.z; As[aCol + 3][r] = v.w;
        }
        #pragma unroll
        for (int p = 0; p < 2; ++p) {
            int r = bRow + p * 8;
            if (MODE == 3) {
                Bs[r][bCol + 0] = Bm[(size_t)(nBase + bCol + 0) * ldb + k0 + r];
                Bs[r][bCol + 1] = Bm[(size_t)(nBase + bCol + 1) * ldb + k0 + r];
                Bs[r][bCol + 2] = Bm[(size_t)(nBase + bCol + 2) * ldb + k0 + r];
                Bs[r][bCol + 3] = Bm[(size_t)(nBase + bCol + 3) * ldb + k0 + r];
            } else {
                float4 v = *(const float4*)(Bm + (size_t)(k0 + r) * ldb + nBase + bCol);
                Bs[r][bCol + 0] = v.x; Bs[r][bCol + 1] = v.y;
                Bs[r][bCol + 2] = v.z; Bs[r][bCol + 3] = v.w;
            }
        }
        __syncthreads();
        #pragma unroll
        for (int kk = 0; kk < 16; ++kk) {
            float ar[8], br[8];
            #pragma unroll
            for (int i = 0; i < 8; i++) ar[i] = As[kk][ty * 8 + i];
            #pragma unroll
            for (int j = 0; j < 8; j++) br[j] = Bs[kk][tx * 8 + j];
            #pragma unroll
            for (int i = 0; i < 8; i++)
                #pragma unroll
                for (int j = 0; j < 8; j++)
                    acc[i][j] = fmaf(ar[i], br[j], acc[i][j]);
        }
        __syncthreads();
    }

    #pragma unroll
    for (int i = 0; i < 8; i++) {
        int m = mBase + ty * 8 + i;
        if (MODE == 4) {
            int lab = labels[m];
            int lo = lab * NNq, hi = lo + NNq;
            #pragma unroll
            for (int j = 0; j < 8; j++) {
                int n = nBase + tx * 8 + j;
                if (n < lo)       Cc[(size_t)m * ldc + n]       = acc[i][j];
                else if (n >= hi) Cc[(size_t)m * ldc + n - NNq] = acc[i][j];
            }
        } else {
            #pragma unroll
            for (int j = 0; j < 8; j += 4) {
                int n = nBase + tx * 8 + j;
                float4 v;
                v.x = acc[i][j + 0]; v.y = acc[i][j + 1];
                v.z = acc[i][j + 2]; v.w = acc[i][j + 3];
                if (bias) {
                    v.x += bias[n]; v.y += bias[n + 1];
                    v.z += bias[n + 2]; v.w += bias[n + 3];
                }
                *(float4*)(Cc + (size_t)m * ldc + n) = v;
            }
        }
    }
}

// ---------------- BN stats: per-feature mean/var over batch --------------
__global__ void bn_stats_k(const float* __restrict__ H,
                           const float* __restrict__ gamma,
                           const float* __restrict__ beta,
                           float* __restrict__ scale, float* __restrict__ shift)
{
    int f = blockIdx.x * 32 + threadIdx.x;
    float s = 0.f, ss = 0.f;
    for (int r = threadIdx.y; r < Bsz; r += 8) {
        float v = H[(size_t)r * DF + f];
        s += v; ss += v * v;
    }
    __shared__ float shs[8][32], shss[8][32];
    shs[threadIdx.y][threadIdx.x]  = s;
    shss[threadIdx.y][threadIdx.x] = ss;
    __syncthreads();
    if (threadIdx.y == 0) {
        #pragma unroll
        for (int y = 1; y < 8; y++) {
            s += shs[y][threadIdx.x]; ss += shss[y][threadIdx.x];
        }
        float mu  = s * (1.f / Bsz);
        float var = ss * (1.f / Bsz) - mu * mu;
        float rst = rsqrtf(var + 1e-5f);
        float sc  = rst * gamma[f];
        scale[f] = sc;
        shift[f] = beta[f] - mu * sc;
    }
}

// ---------------- row l2 normalize (in place), 128 threads/row -----------
__global__ void l2norm_k(float* __restrict__ F)
{
    int b = blockIdx.x, t = threadIdx.x;
    float v = F[(size_t)b * DIM + t];
    float s = v * v;
    #pragma unroll
    for (int o = 16; o; o >>= 1) s += __shfl_xor_sync(0xffffffffu, s, o);
    __shared__ float ws[4];
    if ((t & 31) == 0) ws[t >> 5] = s;
    __syncthreads();
    s = ws[0] + ws[1] + ws[2] + ws[3];
    float inv = 1.f / fmaxf(sqrtf(s), 1e-12f);
    F[(size_t)b * DIM + t] = v * inv;
}

// ---------------- pos_list: 8 dots of dim 128 per row --------------------
__global__ void pos_k(const int* __restrict__ lq, const float* __restrict__ posq,
                      float* __restrict__ out)
{
    int b = blockIdx.x, tid = threadIdx.x;
    __shared__ float fr[DIM];
    if (tid < DIM) fr[tid] = g_featq[(size_t)b * DIM + tid];
    __syncthreads();
    int w = tid >> 5, lane = tid & 31;
    int col = lq[b] * PP + w;
    float s = 0.f;
    for (int d = lane; d < DIM; d += 32)
        s += fr[d] * posq[(size_t)d * PC + col];
    #pragma unroll
    for (int o = 16; o; o >>= 1) s += __shfl_down_sync(0xffffffffu, s, o);
    if (lane == 0) out[OFF_SIM + (size_t)b * SIMW + Bsz + w] = s;
}

// ---------------- labels_con fill (float4 per thread) --------------------
__global__ void labels_fill_k(const int* __restrict__ lq, const int* __restrict__ lk,
                              float* __restrict__ out)
{
    size_t i4 = (size_t)blockIdx.x * blockDim.x + threadIdx.x;
    const size_t total4 = (size_t)Bsz * (SIMW / 4);
    if (i4 >= total4) return;
    int row = (int)(i4 / (SIMW / 4));
    int c0  = (int)(i4 % (SIMW / 4)) * 4;
    float4 v;
    if (c0 + 4 <= Bsz) {
        int l = lq[row];
        v.x = (lk[c0 + 0] == l) ? 1.f : 0.f;
        v.y = (lk[c0 + 1] == l) ? 1.f : 0.f;
        v.z = (lk[c0 + 2] == l) ? 1.f : 0.f;
        v.w = (lk[c0 + 3] == l) ? 1.f : 0.f;
    } else if (c0 >= Bsz && c0 + 4 <= Bsz + PP) {
        v.x = v.y = v.z = v.w = 1.f;
    } else {
        v.x = v.y = v.z = v.w = 0.f;
    }
    *(float4*)(out + OFF_LAB + (size_t)row * SIMW + c0) = v;
}

// ---------------- occurrence rank + per-row class count ------------------
__global__ void rank_k(const int* __restrict__ lk)
{
    __shared__ int sl[Bsz];
    int b = threadIdx.x;
    sl[b] = lk[b];
    __syncthreads();
    int lab = sl[b];
    int r = 0, c = 0;
    for (int j = 0; j < Bsz; j++) {
        int e = (sl[j] == lab);
        c += e;
        r += e & (j < b);
    }
    g_rank[b] = r;
    g_cntb[b] = c;
}

// ---------------- ptr outputs (per-class counts incl. zeros) -------------
__global__ void ptr_k(const int* __restrict__ lk, const int* __restrict__ nptr,
                      const int* __restrict__ pptr, float* __restrict__ out)
{
    __shared__ int sl[Bsz];
    for (int i = threadIdx.x; i < Bsz; i += blockDim.x) sl[i] = lk[i];
    __syncthreads();
    int c = blockIdx.x * blockDim.x + threadIdx.x;
    int cnt = 0;
    for (int j = 0; j < Bsz; j++) cnt += (sl[j] == c);
    out[OFF_NPTR + c] = (float)((nptr[c] + cnt) % NNq);
    out[OFF_PPTR + c] = (float)((pptr[c] + cnt) % PP);
}

// ---------------- queue overwrite: survivors only ------------------------
__global__ void queue_update_k(const int* __restrict__ lk, const int* __restrict__ nptr,
                               const int* __restrict__ pptr, float* __restrict__ out)
{
    int b = blockIdx.x;
    int d = threadIdx.x;   // 128
    int lab = lk[b];
    int r = g_rank[b];
    int c = g_cntb[b];
    float v = g_featk[(size_t)b * DIM + d];
    if (r >= c - NNq) {
        int slot = (nptr[lab] + r) % NNq;
        out[OFF_NQ2 + (size_t)d * NC + lab * NNq + slot] = v;
    }
    if (r >= c - PP) {
        int slot = (pptr[lab] + r) % PP;
        out[OFF_PQ2 + (size_t)d * PC + lab * PP + slot] = v;
    }
}

// ---------------- host launcher -------------------------------------------
static float* symf(const void* sym) {
    void* p = nullptr;
    cudaGetSymbolAddress(&p, sym);
    return (float*)p;
}

extern "C" void kernel_launch(void* const* d_in, const int* in_sizes, int n_in,
                              void* d_out, int out_size)
{
    (void)in_sizes; (void)n_in; (void)out_size;
    const float* midq  = (const float*)d_in[0];
    const float* midk  = (const float*)d_in[1];
    const int*   lq    = (const int*)d_in[2];
    const int*   lk    = (const int*)d_in[3];
    const float* W1    = (const float*)d_in[4];
    const float* b1    = (const float*)d_in[5];
    const float* gamma = (const float*)d_in[6];
    const float* beta  = (const float*)d_in[7];
    const float* W2    = (const float*)d_in[8];
    const float* b2    = (const float*)d_in[9];
    const float* Wlin  = (const float*)d_in[10];
    const float* blin  = (const float*)d_in[11];
    const float* negq  = (const float*)d_in[12];
    const float* posq  = (const float*)d_in[13];
    const int*   nptr  = (const int*)d_in[14];
    const int*   pptr  = (const int*)d_in[15];
    float* out = (float*)d_out;

    float* Hq  = symf(g_Hq);
    float* Hk  = symf(g_Hk);
    float* scq = symf(g_scq); float* shq = symf(g_shq);
    float* sck = symf(g_sck); float* shk = symf(g_shk);
    float* fq  = symf(g_featq);
    float* fk  = symf(g_featk);

    // copy queues to output (updates overwrite below)
    cudaMemcpyAsync(out + OFF_NQ2, negq, sizeof(float) * (size_t)DIM * NC,
                    cudaMemcpyDeviceToDevice);
    cudaMemcpyAsync(out + OFF_PQ2, posq, sizeof(float) * (size_t)DIM * PC,
                    cudaMemcpyDeviceToDevice);

    // H = mid @ W1 + b1
    sgemm_k<0><<<dim3(DF / 128, Bsz / 128), 256>>>(
        midq, W1, b1, Hq, DF, DF, DF, DF, nullptr, nullptr, nullptr);
    sgemm_k<0><<<dim3(DF / 128, Bsz / 128), 256>>>(
        midk, W1, b1, Hk, DF, DF, DF, DF, nullptr, nullptr, nullptr);

    // BN affine params
    bn_stats_k<<<DF / 32, dim3(32, 8)>>>(Hq, gamma, beta, scq, shq);
    bn_stats_k<<<DF / 32, dim3(32, 8)>>>(Hk, gamma, beta, sck, shk);

    // feat = relu(BN(H)) @ W2 + b2, then l2norm rows
    sgemm_k<2><<<dim3(1, Bsz / 128), 256>>>(
        Hq, W2, b2, fq, DF, DF, DIM, DIM, scq, shq, nullptr);
    sgemm_k<2><<<dim3(1, Bsz / 128), 256>>>(
        Hk, W2, b2, fk, DF, DF, DIM, DIM, sck, shk, nullptr);
    l2norm_k<<<Bsz, DIM>>>(fq);
    l2norm_k<<<Bsz, DIM>>>(fk);

    // sim_batch = feat_q @ feat_k^T into sim_con[:, :B]
    sgemm_k<3><<<dim3(Bsz / 128, Bsz / 128), 256>>>(
        fq, fk, nullptr, out + OFF_SIM, DIM, DIM, DIM, SIMW,
        nullptr, nullptr, nullptr);

    // pos_list into sim_con[:, B:B+P]
    pos_k<<<Bsz, 256>>>(lq, posq, out);

    // neg gathered into sim_con[:, B+P:]
    sgemm_k<4><<<dim3(NC / 128, Bsz / 128), 256>>>(
        fq, negq, nullptr, out + OFF_SIM + Bsz + PP, DIM, DIM, NC, SIMW,
        nullptr, nullptr, lq);

    // labels_con
    {
        size_t total4 = (size_t)Bsz * (SIMW / 4);
        int blocks = (int)((total4 + 255) / 256);
        labels_fill_k<<<blocks, 256>>>(lq, lk, out);
    }

    // logits
    sgemm_k<0><<<dim3(CC / 128, Bsz / 128), 256>>>(
        midq, Wlin, blin, out + OFF_LQ, DF, DF, CC, CC, nullptr, nullptr, nullptr);
    sgemm_k<0><<<dim3(CC / 128, Bsz / 128), 256>>>(
        midk, Wlin, blin, out + OFF_LK, DF, DF, CC, CC, nullptr, nullptr, nullptr);

    // queue update machinery
    rank_k<<<1, Bsz>>>(lk);
    ptr_k<<<CC / 256, 256>>>(lk, nptr, pptr, out);
    queue_update_k<<<Bsz, DIM>>>(lk, nptr, pptr, out);
}

// round 2
// speedup vs baseline: 3.5669x; 3.5669x over previous
#include <cuda_runtime.h>
#include <cstddef>
#include <cstdint>

#define Bsz   1024
#define DF    2048
#define DIM   128
#define CC    8192
#define PP    8
#define NNq   4
#define NC    (NNq * CC)            // 32768
#define PC    (PP * CC)             // 65536
#define SIMW  (Bsz + PP + NNq * (CC - 1))  // 33796
#define SPLITK 16

static constexpr size_t OFF_SIM  = 0;
static constexpr size_t OFF_LAB  = (size_t)Bsz * SIMW;
static constexpr size_t OFF_LQ   = OFF_LAB + (size_t)Bsz * SIMW;
static constexpr size_t OFF_LK   = OFF_LQ + (size_t)Bsz * CC;
static constexpr size_t OFF_NQ2  = OFF_LK + (size_t)Bsz * CC;
static constexpr size_t OFF_PQ2  = OFF_NQ2 + (size_t)DIM * NC;
static constexpr size_t OFF_NPTR = OFF_PQ2 + (size_t)DIM * PC;
static constexpr size_t OFF_PPTR = OFF_NPTR + CC;

// ---------------- device scratch (no allocations allowed) ----------------
__device__ float g_Hq[(size_t)Bsz * DF];
__device__ float g_Hk[(size_t)Bsz * DF];
__device__ float g_scq[DF], g_shq[DF], g_sck[DF], g_shk[DF];
__device__ float g_featq[(size_t)Bsz * DIM];
__device__ float g_featk[(size_t)Bsz * DIM];
__device__ float g_fpart[(size_t)2 * SPLITK * Bsz * DIM];
__device__ int   g_rank[Bsz];
__device__ int   g_cntb[Bsz];

// ---------------- tf32 helpers -------------------------------------------
__device__ __forceinline__ unsigned f2tf(float x) {
    unsigned u;
    asm("cvt.rna.tf32.f32 %0, %1;" : "=r"(u) : "f"(x));
    return u;
}

__device__ __forceinline__ void mma_tf32(float c[4], const unsigned a[4],
                                         const unsigned b[2]) {
    asm volatile(
        "mma.sync.aligned.m16n8k8.row.col.f32.tf32.tf32.f32 "
        "{%0,%1,%2,%3}, {%4,%5,%6,%7}, {%8,%9}, {%0,%1,%2,%3};"
        : "+f"(c[0]), "+f"(c[1]), "+f"(c[2]), "+f"(c[3])
        : "r"(a[0]), "r"(a[1]), "r"(a[2]), "r"(a[3]), "r"(b[0]), "r"(b[1]));
}

// ---------------- TF32 tensor-core GEMM ----------------------------------
// 128x128 block tile, BK=32, 256 threads (8 warps, warp tile 64x32).
// MODE 0: C = A@B + bias.              z selects (A0,C0) vs (A1,C1)
// MODE 2: A' = relu(A*sc+sh) on load;  z = qk*SPLITK + sk (split-K partials)
// MODE 3: B transposed (B[k][n] = Bm[n*ldb+k]); no bias
// MODE 4: neg epilogue: scatter skipping labels[m]'s NNq columns
template <int MODE>
__global__ __launch_bounds__(256, 2) void tgemm_k(
    const float* __restrict__ A0, const float* __restrict__ A1,
    const float* __restrict__ Bm, const float* __restrict__ bias,
    float* __restrict__ C0, float* __restrict__ C1,
    int K, int lda, int ldb, int ldc,
    const float* __restrict__ sc0, const float* __restrict__ sh0,
    const float* __restrict__ sc1, const float* __restrict__ sh1,
    const int* __restrict__ labels)
{
    __shared__ unsigned As[32 * 136];
    __shared__ unsigned Bs[32 * 136];

    const int tid   = threadIdx.x;
    const int mBase = blockIdx.y * 128;
    const int nBase = blockIdx.x * 128;
    const int lane  = tid & 31;
    const int warp  = tid >> 5;
    const int g     = lane >> 2;   // group 0..7
    const int tig   = lane & 3;    // thread-in-group
    const int wm    = (warp & 1) * 64;
    const int wn    = (warp >> 1) * 32;

    int qk = 0, kBeg = 0, kEnd = K;
    const float* A;
    float* Cc;
    const float* sc = nullptr;
    const float* sh = nullptr;
    if (MODE == 2) {
        qk = blockIdx.z >> 4;
        int skc = blockIdx.z & 15;
        kBeg = skc * (K / SPLITK);
        kEnd = kBeg + K / SPLITK;
        A  = qk ? A1 : A0;
        sc = qk ? sc1 : sc0;
        sh = qk ? sh1 : sh0;
        Cc = C0 + (size_t)blockIdx.z * ((size_t)Bsz * DIM);
    } else {
        qk = blockIdx.z;
        A  = qk ? A1 : A0;
        Cc = qk ? C1 : C0;
    }

    float acc[4][4][4] = {};

    const int am  = tid >> 1;          // 0..127 row for A-style loads
    const int akq = (tid & 1) * 16;    // k quarter base
    const int bk  = tid >> 3;          // 0..31 row for B-style loads
    const int bnq = (tid & 7) * 4;     // n base

    for (int k0 = kBeg; k0 < kEnd; k0 += 32) {
        // ---- stage A tile into As[k][m] (pad 136) ----
        #pragma unroll
        for (int i = 0; i < 4; i++) {
            int k = akq + i * 4;
            float4 v = *(const float4*)(A + (size_t)(mBase + am) * lda + k0 + k);
            if (MODE == 2) {
                float4 s4 = *(const float4*)(sc + k0 + k);
                float4 h4 = *(const float4*)(sh + k0 + k);
                v.x = fmaxf(fmaf(v.x, s4.x, h4.x), 0.f);
                v.y = fmaxf(fmaf(v.y, s4.y, h4.y), 0.f);
                v.z = fmaxf(fmaf(v.z, s4.z, h4.z), 0.f);
                v.w = fmaxf(fmaf(v.w, s4.w, h4.w), 0.f);
            }
            As[(k + 0) * 136 + am] = f2tf(v.x);
            As[(k + 1) * 136 + am] = f2tf(v.y);
            As[(k + 2) * 136 + am] = f2tf(v.z);
            As[(k + 3) * 136 + am] = f2tf(v.w);
        }
        // ---- stage B tile into Bs[k][n] ----
        if (MODE == 3) {
            #pragma unroll
            for (int i = 0; i < 4; i++) {
                int k = akq + i * 4;
                float4 v = *(const float4*)(Bm + (size_t)(nBase + am) * ldb + k0 + k);
                Bs[(k + 0) * 136 + am] = f2tf(v.x);
                Bs[(k + 1) * 136 + am] = f2tf(v.y);
                Bs[(k + 2) * 136 + am] = f2tf(v.z);
                Bs[(k + 3) * 136 + am] = f2tf(v.w);
            }
        } else {
            #pragma unroll
            for (int i = 0; i < 4; i++) {
                int n = bnq + i * 32;
                float4 v = *(const float4*)(Bm + (size_t)(k0 + bk) * ldb + nBase + n);
                uint4 u;
                u.x = f2tf(v.x); u.y = f2tf(v.y);
                u.z = f2tf(v.z); u.w = f2tf(v.w);
                *(uint4*)&Bs[bk * 136 + n] = u;
            }
        }
        __syncthreads();

        // ---- mma over 4 k-steps of 8 ----
        #pragma unroll
        for (int kk = 0; kk < 32; kk += 8) {
            unsigned af[4][4], bf[4][2];
            #pragma unroll
            for (int mt = 0; mt < 4; mt++) {
                int mr = wm + mt * 16 + g;
                af[mt][0] = As[(kk + tig) * 136 + mr];
                af[mt][1] = As[(kk + tig) * 136 + mr + 8];
                af[mt][2] = As[(kk + tig + 4) * 136 + mr];
                af[mt][3] = As[(kk + tig + 4) * 136 + mr + 8];
            }
            #pragma unroll
            for (int nt = 0; nt < 4; nt++) {
                int nc = wn + nt * 8 + g;
                bf[nt][0] = Bs[(kk + tig) * 136 + nc];
                bf[nt][1] = Bs[(kk + tig + 4) * 136 + nc];
            }
            #pragma unroll
            for (int mt = 0; mt < 4; mt++)
                #pragma unroll
                for (int nt = 0; nt < 4; nt++)
                    mma_tf32(acc[mt][nt], af[mt], bf[nt]);
        }
        __syncthreads();
    }

    // ---- epilogue ----
    #pragma unroll
    for (int mt = 0; mt < 4; mt++) {
        int r0 = mBase + wm + mt * 16 + g;
        int r1 = r0 + 8;
        int la0 = 0, la1 = 0;
        if (MODE == 4) { la0 = labels[r0] * NNq; la1 = labels[r1] * NNq; }
        #pragma unroll
        for (int nt = 0; nt < 4; nt++) {
            int c = nBase + wn + nt * 8 + 2 * tig;
            const float* a4 = acc[mt][nt];
            if (MODE == 4) {
                int n0 = c, n1 = c + 1;
                if (n0 < la0)            Cc[(size_t)r0 * ldc + n0]       = a4[0];
                else if (n0 >= la0 + NNq) Cc[(size_t)r0 * ldc + n0 - NNq] = a4[0];
                if (n1 < la0)            Cc[(size_t)r0 * ldc + n1]       = a4[1];
                else if (n1 >= la0 + NNq) Cc[(size_t)r0 * ldc + n1 - NNq] = a4[1];
                if (n0 < la1)            Cc[(size_t)r1 * ldc + n0]       = a4[2];
                else if (n0 >= la1 + NNq) Cc[(size_t)r1 * ldc + n0 - NNq] = a4[2];
                if (n1 < la1)            Cc[(size_t)r1 * ldc + n1]       = a4[3];
                else if (n1 >= la1 + NNq) Cc[(size_t)r1 * ldc + n1 - NNq] = a4[3];
            } else {
                float bx = 0.f, by = 0.f;
                if (MODE == 0) { bx = bias[c]; by = bias[c + 1]; }
                float2 v0 = { a4[0] + bx, a4[1] + by };
                float2 v1 = { a4[2] + bx, a4[3] + by };
                *(float2*)(Cc + (size_t)r0 * ldc + c) = v0;
                *(float2*)(Cc + (size_t)r1 * ldc + c) = v1;
            }
        }
    }
}

// ---------------- BN stats: per-feature scale/shift ----------------------
__global__ void bn_stats_k(const float* __restrict__ Hq, const float* __restrict__ Hk,
                           const float* __restrict__ gamma, const float* __restrict__ beta,
                           float* __restrict__ scq, float* __restrict__ shq,
                           float* __restrict__ sck, float* __restrict__ shk)
{
    const float* H = blockIdx.z ? Hk : Hq;
    float* scale = blockIdx.z ? sck : scq;
    float* shift = blockIdx.z ? shk : shq;
    int f = blockIdx.x * 32 + threadIdx.x;
    float s = 0.f, ss = 0.f;
    for (int r = threadIdx.y; r < Bsz; r += 32) {
        float v = H[(size_t)r * DF + f];
        s += v; ss += v * v;
    }
    __shared__ float sh_s[32][33], sh_ss[32][33];
    sh_s[threadIdx.y][threadIdx.x]  = s;
    sh_ss[threadIdx.y][threadIdx.x] = ss;
    __syncthreads();
    if (threadIdx.y == 0) {
        #pragma unroll
        for (int y = 1; y < 32; y++) {
            s += sh_s[y][threadIdx.x]; ss += sh_ss[y][threadIdx.x];
        }
        float mu  = s * (1.f / Bsz);
        float var = ss * (1.f / Bsz) - mu * mu;
        float rst = rsqrtf(var + 1e-5f);
        float scv = rst * gamma[f];
        scale[f] = scv;
        shift[f] = beta[f] - mu * scv;
    }
}

// ---------------- split-K reduce + bias + row l2norm ----------------------
__global__ void reduce_l2_k(const float* __restrict__ b2)
{
    int qk = blockIdx.y, b = blockIdx.x, d = threadIdx.x;  // d: 0..127
    const float* part = g_fpart + (size_t)qk * SPLITK * Bsz * DIM;
    float v = b2[d];
    #pragma unroll
    for (int s = 0; s < SPLITK; s++)
        v += part[(size_t)s * Bsz * DIM + (size_t)b * DIM + d];
    float ss = v * v;
    #pragma unroll
    for (int o = 16; o; o >>= 1) ss += __shfl_xor_sync(0xffffffffu, ss, o);
    __shared__ float ws[4];
    if ((d & 31) == 0) ws[d >> 5] = ss;
    __syncthreads();
    ss = ws[0] + ws[1] + ws[2] + ws[3];
    float inv = 1.f / fmaxf(sqrtf(ss), 1e-12f);
    float* dst = qk ? g_featk : g_featq;
    dst[(size_t)b * DIM + d] = v * inv;
}

// ---------------- pos_list: 8 dots of dim 128 per row --------------------
__global__ void pos_k(const int* __restrict__ lq, const float* __restrict__ posq,
                      float* __restrict__ out)
{
    int b = blockIdx.x, tid = threadIdx.x;
    __shared__ float fr[DIM];
    if (tid < DIM) fr[tid] = g_featq[(size_t)b * DIM + tid];
    __syncthreads();
    int w = tid >> 5, lane = tid & 31;
    int col = lq[b] * PP + w;
    float s = 0.f;
    for (int d = lane; d < DIM; d += 32)
        s += fr[d] * posq[(size_t)d * PC + col];
    #pragma unroll
    for (int o = 16; o; o >>= 1) s += __shfl_down_sync(0xffffffffu, s, o);
    if (lane == 0) out[OFF_SIM + (size_t)b * SIMW + Bsz + w] = s;
}

// ---------------- labels_con fill (float4 per thread) --------------------
__global__ void labels_fill_k(const int* __restrict__ lq, const int* __restrict__ lk,
                              float* __restrict__ out)
{
    size_t i4 = (size_t)blockIdx.x * blockDim.x + threadIdx.x;
    const size_t total4 = (size_t)Bsz * (SIMW / 4);
    if (i4 >= total4) return;
    int row = (int)(i4 / (SIMW / 4));
    int c0  = (int)(i4 % (SIMW / 4)) * 4;
    float4 v;
    if (c0 + 4 <= Bsz) {
        int l = lq[row];
        v.x = (lk[c0 + 0] == l) ? 1.f : 0.f;
        v.y = (lk[c0 + 1] == l) ? 1.f : 0.f;
        v.z = (lk[c0 + 2] == l) ? 1.f : 0.f;
        v.w = (lk[c0 + 3] == l) ? 1.f : 0.f;
    } else if (c0 >= Bsz && c0 + 4 <= Bsz + PP) {
        v.x = v.y = v.z = v.w = 1.f;
    } else {
        v.x = v.y = v.z = v.w = 0.f;
    }
    *(float4*)(out + OFF_LAB + (size_t)row * SIMW + c0) = v;
}

// ---------------- occurrence rank + per-row class count ------------------
__global__ void rank_k(const int* __restrict__ lk)
{
    __shared__ int sl[Bsz];
    int b = threadIdx.x;
    sl[b] = lk[b];
    __syncthreads();
    int lab = sl[b];
    int r = 0, c = 0;
    for (int j = 0; j < Bsz; j++) {
        int e = (sl[j] == lab);
        c += e;
        r += e & (j < b);
    }
    g_rank[b] = r;
    g_cntb[b] = c;
}

// ---------------- ptr outputs --------------------------------------------
__global__ void ptr_k(const int* __restrict__ lk, const int* __restrict__ nptr,
                      const int* __restrict__ pptr, float* __restrict__ out)
{
    __shared__ int sl[Bsz];
    for (int i = threadIdx.x; i < Bsz; i += blockDim.x) sl[i] = lk[i];
    __syncthreads();
    int c = blockIdx.x * blockDim.x + threadIdx.x;
    int cnt = 0;
    for (int j = 0; j < Bsz; j++) cnt += (sl[j] == c);
    out[OFF_NPTR + c] = (float)((nptr[c] + cnt) % NNq);
    out[OFF_PPTR + c] = (float)((pptr[c] + cnt) % PP);
}

// ---------------- queue overwrite: survivors only ------------------------
__global__ void queue_update_k(const int* __restrict__ lk, const int* __restrict__ nptr,
                               const int* __restrict__ pptr, float* __restrict__ out)
{
    int b = blockIdx.x;
    int d = threadIdx.x;   // 128
    int lab = lk[b];
    int r = g_rank[b];
    int c = g_cntb[b];
    float v = g_featk[(size_t)b * DIM + d];
    if (r >= c - NNq) {
        int slot = (nptr[lab] + r) % NNq;
        out[OFF_NQ2 + (size_t)d * NC + lab * NNq + slot] = v;
    }
    if (r >= c - PP) {
        int slot = (pptr[lab] + r) % PP;
        out[OFF_PQ2 + (size_t)d * PC + lab * PP + slot] = v;
    }
}

// ---------------- host launcher -------------------------------------------
static float* symf(const void* sym) {
    void* p = nullptr;
    cudaGetSymbolAddress(&p, sym);
    return (float*)p;
}

extern "C" void kernel_launch(void* const* d_in, const int* in_sizes, int n_in,
                              void* d_out, int out_size)
{
    (void)in_sizes; (void)n_in; (void)out_size;
    const float* midq  = (const float*)d_in[0];
    const float* midk  = (const float*)d_in[1];
    const int*   lq    = (const int*)d_in[2];
    const int*   lk    = (const int*)d_in[3];
    const float* W1    = (const float*)d_in[4];
    const float* b1    = (const float*)d_in[5];
    const float* gamma = (const float*)d_in[6];
    const float* beta  = (const float*)d_in[7];
    const float* W2    = (const float*)d_in[8];
    const float* b2    = (const float*)d_in[9];
    const float* Wlin  = (const float*)d_in[10];
    const float* blin  = (const float*)d_in[11];
    const float* negq  = (const float*)d_in[12];
    const float* posq  = (const float*)d_in[13];
    const int*   nptr  = (const int*)d_in[14];
    const int*   pptr  = (const int*)d_in[15];
    float* out = (float*)d_out;

    float* Hq  = symf(g_Hq);
    float* Hk  = symf(g_Hk);
    float* scq = symf(g_scq); float* shq = symf(g_shq);
    float* sck = symf(g_sck); float* shk = symf(g_shk);
    float* fq  = symf(g_featq);
    float* fk  = symf(g_featk);
    float* fpart = symf(g_fpart);

    // copy queues to output (updates overwrite below)
    cudaMemcpyAsync(out + OFF_NQ2, negq, sizeof(float) * (size_t)DIM * NC,
                    cudaMemcpyDeviceToDevice);
    cudaMemcpyAsync(out + OFF_PQ2, posq, sizeof(float) * (size_t)DIM * PC,
                    cudaMemcpyDeviceToDevice);

    // logits: mid @ Wlin + blin (independent — launch early, big)
    tgemm_k<0><<<dim3(CC / 128, Bsz / 128, 2), 256>>>(
        midq, midk, Wlin, blin, out + OFF_LQ, out + OFF_LK,
        DF, DF, CC, CC, nullptr, nullptr, nullptr, nullptr, nullptr);

    // H = mid @ W1 + b1 (q and k batched via z)
    tgemm_k<0><<<dim3(DF / 128, Bsz / 128, 2), 256>>>(
        midq, midk, W1, b1, Hq, Hk,
        DF, DF, DF, DF, nullptr, nullptr, nullptr, nullptr, nullptr);

    // BN affine params (q and k batched via z)
    bn_stats_k<<<dim3(DF / 32, 1, 2), dim3(32, 32)>>>(
        Hq, Hk, gamma, beta, scq, shq, sck, shk);

    // feat partials = relu(BN(H)) @ W2 (split-K=16, q/k via z)
    tgemm_k<2><<<dim3(1, Bsz / 128, 2 * SPLITK), 256>>>(
        Hq, Hk, W2, nullptr, fpart, nullptr,
        DF, DF, DIM, DIM, scq, shq, sck, shk, nullptr);

    // reduce partials + bias + l2norm
    reduce_l2_k<<<dim3(Bsz, 2), DIM>>>(b2);

    // sim_batch = feat_q @ feat_k^T
    tgemm_k<3><<<dim3(Bsz / 128, Bsz / 128, 1), 256>>>(
        fq, nullptr, fk, nullptr, out + OFF_SIM, nullptr,
        DIM, DIM, DIM, SIMW, nullptr, nullptr, nullptr, nullptr, nullptr);

    // pos_list into sim_con[:, B:B+P]
    pos_k<<<Bsz, 256>>>(lq, posq, out);

    // neg gathered into sim_con[:, B+P:]
    tgemm_k<4><<<dim3(NC / 128, Bsz / 128, 1), 256>>>(
        fq, nullptr, negq, nullptr, out + OFF_SIM + Bsz + PP, nullptr,
        DIM, DIM, NC, SIMW, nullptr, nullptr, nullptr, nullptr, lq);

    // labels_con
    {
        size_t total4 = (size_t)Bsz * (SIMW / 4);
        int blocks = (int)((total4 + 255) / 256);
        labels_fill_k<<<blocks, 256>>>(lq, lk, out);
    }

    // queue update machinery
    rank_k<<<1, Bsz>>>(lk);
    ptr_k<<<CC / 256, 256>>>(lk, nptr, pptr, out);
    queue_update_k<<<Bsz, DIM>>>(lk, nptr, pptr, out);
}

// round 3
// speedup vs baseline: 4.3425x; 1.2174x over previous
#include <cuda_runtime.h>
#include <cstddef>
#include <cstdint>

#define Bsz   1024
#define DF    2048
#define DIM   128
#define CC    8192
#define PP    8
#define NNq   4
#define NC    (NNq * CC)            // 32768
#define PC    (PP * CC)             // 65536
#define SIMW  (Bsz + PP + NNq * (CC - 1))  // 33796
#define SPLITK 16

static constexpr size_t OFF_SIM  = 0;
static constexpr size_t OFF_LAB  = (size_t)Bsz * SIMW;
static constexpr size_t OFF_LQ   = OFF_LAB + (size_t)Bsz * SIMW;
static constexpr size_t OFF_LK   = OFF_LQ + (size_t)Bsz * CC;
static constexpr size_t OFF_NQ2  = OFF_LK + (size_t)Bsz * CC;
static constexpr size_t OFF_PQ2  = OFF_NQ2 + (size_t)DIM * NC;
static constexpr size_t OFF_NPTR = OFF_PQ2 + (size_t)DIM * PC;
static constexpr size_t OFF_PPTR = OFF_NPTR + CC;

// ---------------- device scratch (no allocations allowed) ----------------
__device__ float g_Hq[(size_t)Bsz * DF];
__device__ float g_Hk[(size_t)Bsz * DF];
__device__ float g_scq[DF], g_shq[DF], g_sck[DF], g_shk[DF];
__device__ float g_featq[(size_t)Bsz * DIM];
__device__ float g_featk[(size_t)Bsz * DIM];
__device__ float g_fpart[(size_t)2 * SPLITK * Bsz * DIM];
__device__ int   g_rank[Bsz];
__device__ int   g_cntb[Bsz];

// ---------------- helpers -------------------------------------------------
__device__ __forceinline__ unsigned f2tf(float x) {
    unsigned u;
    asm("cvt.rna.tf32.f32 %0, %1;" : "=r"(u) : "f"(x));
    return u;
}

__device__ __forceinline__ void mma_tf32(float c[4], const unsigned a[4],
                                         const unsigned b[2]) {
    asm volatile(
        "mma.sync.aligned.m16n8k8.row.col.f32.tf32.tf32.f32 "
        "{%0,%1,%2,%3}, {%4,%5,%6,%7}, {%8,%9}, {%0,%1,%2,%3};"
        : "+f"(c[0]), "+f"(c[1]), "+f"(c[2]), "+f"(c[3])
        : "r"(a[0]), "r"(a[1]), "r"(a[2]), "r"(a[3]), "r"(b[0]), "r"(b[1]));
}

__device__ __forceinline__ void cpa16(uint32_t saddr, const float* g) {
    asm volatile("cp.async.cg.shared.global [%0], [%1], 16;\n"
                 :: "r"(saddr), "l"(g));
}
#define CP_COMMIT() asm volatile("cp.async.commit_group;\n" ::: "memory")
#define CP_WAIT1()  asm volatile("cp.async.wait_group 1;\n" ::: "memory")
#define CP_WAIT0()  asm volatile("cp.async.wait_group 0;\n" ::: "memory")

// ---------------- TF32 tensor-core GEMM, cp.async double-buffered ---------
// 128x128 block tile, BK=16, 256 threads (8 warps, warp tile 64x32).
// As layout [m][k] stride 20 (frag banks 20g+tig: conflict-free)
// Bs layout [k][n] stride 136 (frag banks 8t+g: conflict-free)
// MODE 0: C = A@B + bias.              z selects (A0,C0) vs (A1,C1)
// MODE 2: A' = relu(A*sc+sh) at frag read; z = qk*SPLITK + sk partials
// MODE 3: B transposed (B[k][n] = Bm[n*ldb+k]); no bias
// MODE 4: neg epilogue: scatter skipping labels[m]'s NNq columns
#define ASTR 20
#define BSTR 136
template <int MODE>
__global__ __launch_bounds__(256, 2) void tgemm_k(
    const float* __restrict__ A0, const float* __restrict__ A1,
    const float* __restrict__ Bm, const float* __restrict__ bias,
    float* __restrict__ C0, float* __restrict__ C1,
    int K, int lda, int ldb, int ldc,
    const float* __restrict__ sc0, const float* __restrict__ sh0,
    const float* __restrict__ sc1, const float* __restrict__ sh1,
    const int* __restrict__ labels)
{
    __shared__ float As[2][128 * ASTR];
    __shared__ float Bs[2][16 * BSTR];
    __shared__ float scs[2][16], shs[2][16];

    const int tid   = threadIdx.x;
    const int mBase = blockIdx.y * 128;
    const int nBase = blockIdx.x * 128;
    const int lane  = tid & 31;
    const int warp  = tid >> 5;
    const int g     = lane >> 2;
    const int tig   = lane & 3;
    const int wm    = (warp & 1) * 64;
    const int wn    = (warp >> 1) * 32;

    int kBeg = 0, kEnd = K;
    const float* A;
    float* Cc;
    const float* sc = nullptr;
    const float* sh = nullptr;
    if (MODE == 2) {
        int qk  = blockIdx.z >> 4;
        int skc = blockIdx.z & 15;
        kBeg = skc * (K / SPLITK);
        kEnd = kBeg + K / SPLITK;
        A  = qk ? A1 : A0;
        sc = qk ? sc1 : sc0;
        sh = qk ? sh1 : sh0;
        Cc = C0 + (size_t)blockIdx.z * ((size_t)Bsz * DIM);
    } else {
        A  = blockIdx.z ? A1 : A0;
        Cc = blockIdx.z ? C1 : C0;
    }

    uint32_t asA = (uint32_t)__cvta_generic_to_shared(&As[0][0]);
    uint32_t asB = (uint32_t)__cvta_generic_to_shared(&Bs[0][0]);

    // staging coordinates
    const int amc = tid >> 2;            // A chunk row (per 256-chunk pass)
    const int akc = (tid & 3) << 2;      // A chunk k-offset
    const int bkc = tid >> 5;            // B chunk row
    const int bnc = (tid & 31) << 2;     // B chunk n-offset

    auto load_tiles = [&](int s, int kpos) {
        // A: 128x16 floats = 512 chunks; 2 per thread
        #pragma unroll
        for (int i = 0; i < 2; i++) {
            int m = amc + i * 64;
            cpa16(asA + (uint32_t)((s * 128 * ASTR + m * ASTR + akc) * 4),
                  A + (size_t)(mBase + m) * lda + kpos + akc);
        }
        if (MODE != 3) {
            // B: 16x128 floats = 512 chunks; 2 per thread
            #pragma unroll
            for (int i = 0; i < 2; i++) {
                int k = bkc + i * 8;
                cpa16(asB + (uint32_t)((s * 16 * BSTR + k * BSTR + bnc) * 4),
                      Bm + (size_t)(kpos + k) * ldb + nBase + bnc);
            }
        } else {
            // transposed staging via regular ld/st (tiny GEMM)
            int n  = tid >> 1;
            int kq = (tid & 1) * 8;
            float4 v0 = *(const float4*)(Bm + (size_t)(nBase + n) * ldb + kpos + kq);
            float4 v1 = *(const float4*)(Bm + (size_t)(nBase + n) * ldb + kpos + kq + 4);
            Bs[s][(kq + 0) * BSTR + n] = v0.x;
            Bs[s][(kq + 1) * BSTR + n] = v0.y;
            Bs[s][(kq + 2) * BSTR + n] = v0.z;
            Bs[s][(kq + 3) * BSTR + n] = v0.w;
            Bs[s][(kq + 4) * BSTR + n] = v1.x;
            Bs[s][(kq + 5) * BSTR + n] = v1.y;
            Bs[s][(kq + 6) * BSTR + n] = v1.z;
            Bs[s][(kq + 7) * BSTR + n] = v1.w;
        }
        if (MODE == 2 && tid < 8) {
            const float* src = (tid < 4) ? sc : sh;
            float* dst = (tid < 4) ? scs[s] : shs[s];
            int t = tid & 3;
            *(float4*)(dst + t * 4) = *(const float4*)(src + kpos + t * 4);
        }
    };

    float acc[4][4][4] = {};

    const int nIter = (kEnd - kBeg) / 16;
    load_tiles(0, kBeg);
    CP_COMMIT();

    for (int it = 0; it < nIter; ++it) {
        int s = it & 1;
        if (it + 1 < nIter) {
            load_tiles(s ^ 1, kBeg + (it + 1) * 16);
            CP_COMMIT();
            CP_WAIT1();
        } else {
            CP_WAIT0();
        }
        __syncthreads();

        const float* as = As[s];
        const float* bs = Bs[s];
        #pragma unroll
        for (int kk = 0; kk < 16; kk += 8) {
            float c0 = 0.f, c1 = 0.f, d0 = 0.f, d1 = 0.f;
            if (MODE == 2) {
                c0 = scs[s][kk + tig];     d0 = shs[s][kk + tig];
                c1 = scs[s][kk + tig + 4]; d1 = shs[s][kk + tig + 4];
            }
            unsigned af[4][4], bf[4][2];
            #pragma unroll
            for (int mt = 0; mt < 4; mt++) {
                int mr = wm + mt * 16 + g;
                float a0 = as[mr * ASTR + kk + tig];
                float a1 = as[(mr + 8) * ASTR + kk + tig];
                float a2 = as[mr * ASTR + kk + tig + 4];
                float a3 = as[(mr + 8) * ASTR + kk + tig + 4];
                if (MODE == 2) {
                    a0 = fmaxf(fmaf(a0, c0, d0), 0.f);
                    a1 = fmaxf(fmaf(a1, c0, d0), 0.f);
                    a2 = fmaxf(fmaf(a2, c1, d1), 0.f);
                    a3 = fmaxf(fmaf(a3, c1, d1), 0.f);
                }
                af[mt][0] = f2tf(a0); af[mt][1] = f2tf(a1);
                af[mt][2] = f2tf(a2); af[mt][3] = f2tf(a3);
            }
            #pragma unroll
            for (int nt = 0; nt < 4; nt++) {
                int nc = wn + nt * 8 + g;
                bf[nt][0] = f2tf(bs[(kk + tig) * BSTR + nc]);
                bf[nt][1] = f2tf(bs[(kk + tig + 4) * BSTR + nc]);
            }
            #pragma unroll
            for (int mt = 0; mt < 4; mt++)
                #pragma unroll
                for (int nt = 0; nt < 4; nt++)
                    mma_tf32(acc[mt][nt], af[mt], bf[nt]);
        }
        __syncthreads();
    }

    // ---- epilogue ----
    #pragma unroll
    for (int mt = 0; mt < 4; mt++) {
        int r0 = mBase + wm + mt * 16 + g;
        int r1 = r0 + 8;
        int la0 = 0, la1 = 0;
        if (MODE == 4) { la0 = labels[r0] * NNq; la1 = labels[r1] * NNq; }
        #pragma unroll
        for (int nt = 0; nt < 4; nt++) {
            int c = nBase + wn + nt * 8 + 2 * tig;
            const float* a4 = acc[mt][nt];
            if (MODE == 4) {
                int n0 = c, n1 = c + 1;
                if (n0 < la0)             Cc[(size_t)r0 * ldc + n0]       = a4[0];
                else if (n0 >= la0 + NNq) Cc[(size_t)r0 * ldc + n0 - NNq] = a4[0];
                if (n1 < la0)             Cc[(size_t)r0 * ldc + n1]       = a4[1];
                else if (n1 >= la0 + NNq) Cc[(size_t)r0 * ldc + n1 - NNq] = a4[1];
                if (n0 < la1)             Cc[(size_t)r1 * ldc + n0]       = a4[2];
                else if (n0 >= la1 + NNq) Cc[(size_t)r1 * ldc + n0 - NNq] = a4[2];
                if (n1 < la1)             Cc[(size_t)r1 * ldc + n1]       = a4[3];
                else if (n1 >= la1 + NNq) Cc[(size_t)r1 * ldc + n1 - NNq] = a4[3];
            } else {
                float bx = 0.f, by = 0.f;
                if (MODE == 0) { bx = bias[c]; by = bias[c + 1]; }
                float2 v0 = { a4[0] + bx, a4[1] + by };
                float2 v1 = { a4[2] + bx, a4[3] + by };
                *(float2*)(Cc + (size_t)r0 * ldc + c) = v0;
                *(float2*)(Cc + (size_t)r1 * ldc + c) = v1;
            }
        }
    }
}

// ---------------- BN stats: per-feature scale/shift ----------------------
__global__ void bn_stats_k(const float* __restrict__ Hq, const float* __restrict__ Hk,
                           const float* __restrict__ gamma, const float* __restrict__ beta,
                           float* __restrict__ scq, float* __restrict__ shq,
                           float* __restrict__ sck, float* __restrict__ shk)
{
    const float* H = blockIdx.z ? Hk : Hq;
    float* scale = blockIdx.z ? sck : scq;
    float* shift = blockIdx.z ? shk : shq;
    int f = blockIdx.x * 32 + threadIdx.x;
    float s = 0.f, ss = 0.f;
    for (int r = threadIdx.y; r < Bsz; r += 32) {
        float v = H[(size_t)r * DF + f];
        s += v; ss += v * v;
    }
    __shared__ float sh_s[32][33], sh_ss[32][33];
    sh_s[threadIdx.y][threadIdx.x]  = s;
    sh_ss[threadIdx.y][threadIdx.x] = ss;
    __syncthreads();
    if (threadIdx.y == 0) {
        #pragma unroll
        for (int y = 1; y < 32; y++) {
            s += sh_s[y][threadIdx.x]; ss += sh_ss[y][threadIdx.x];
        }
        float mu  = s * (1.f / Bsz);
        float var = ss * (1.f / Bsz) - mu * mu;
        float rst = rsqrtf(var + 1e-5f);
        float scv = rst * gamma[f];
        scale[f] = scv;
        shift[f] = beta[f] - mu * scv;
    }
}

// ---------------- split-K reduce + bias + row l2norm ----------------------
__global__ void reduce_l2_k(const float* __restrict__ b2)
{
    int qk = blockIdx.y, b = blockIdx.x, d = threadIdx.x;  // d: 0..127
    const float* part = g_fpart + (size_t)qk * SPLITK * Bsz * DIM;
    float v = b2[d];
    #pragma unroll
    for (int s = 0; s < SPLITK; s++)
        v += part[(size_t)s * Bsz * DIM + (size_t)b * DIM + d];
    float ss = v * v;
    #pragma unroll
    for (int o = 16; o; o >>= 1) ss += __shfl_xor_sync(0xffffffffu, ss, o);
    __shared__ float ws[4];
    if ((d & 31) == 0) ws[d >> 5] = ss;
    __syncthreads();
    ss = ws[0] + ws[1] + ws[2] + ws[3];
    float inv = 1.f / fmaxf(sqrtf(ss), 1e-12f);
    float* dst = qk ? g_featk : g_featq;
    dst[(size_t)b * DIM + d] = v * inv;
}

// ---------------- pos_list: 8 dots of dim 128 per row --------------------
__global__ void pos_k(const int* __restrict__ lq, const float* __restrict__ posq,
                      float* __restrict__ out)
{
    int b = blockIdx.x, tid = threadIdx.x;
    __shared__ float fr[DIM];
    if (tid < DIM) fr[tid] = g_featq[(size_t)b * DIM + tid];
    __syncthreads();
    int w = tid >> 5, lane = tid & 31;
    int col = lq[b] * PP + w;
    float s = 0.f;
    for (int d = lane; d < DIM; d += 32)
        s += fr[d] * posq[(size_t)d * PC + col];
    #pragma unroll
    for (int o = 16; o; o >>= 1) s += __shfl_down_sync(0xffffffffu, s, o);
    if (lane == 0) out[OFF_SIM + (size_t)b * SIMW + Bsz + w] = s;
}

// ---------------- labels_con fill (float4 per thread) --------------------
__global__ void labels_fill_k(const int* __restrict__ lq, const int* __restrict__ lk,
                              float* __restrict__ out)
{
    size_t i4 = (size_t)blockIdx.x * blockDim.x + threadIdx.x;
    const size_t total4 = (size_t)Bsz * (SIMW / 4);
    if (i4 >= total4) return;
    int row = (int)(i4 / (SIMW / 4));
    int c0  = (int)(i4 % (SIMW / 4)) * 4;
    float4 v;
    if (c0 + 4 <= Bsz) {
        int l = lq[row];
        v.x = (lk[c0 + 0] == l) ? 1.f : 0.f;
        v.y = (lk[c0 + 1] == l) ? 1.f : 0.f;
        v.z = (lk[c0 + 2] == l) ? 1.f : 0.f;
        v.w = (lk[c0 + 3] == l) ? 1.f : 0.f;
    } else if (c0 >= Bsz && c0 + 4 <= Bsz + PP) {
        v.x = v.y = v.z = v.w = 1.f;
    } else {
        v.x = v.y = v.z = v.w = 0.f;
    }
    *(float4*)(out + OFF_LAB + (size_t)row * SIMW + c0) = v;
}

// ---------------- occurrence rank + per-row class count ------------------
__global__ void rank_k(const int* __restrict__ lk)
{
    __shared__ int sl[Bsz];
    int b = threadIdx.x;
    sl[b] = lk[b];
    __syncthreads();
    int lab = sl[b];
    int r = 0, c = 0;
    for (int j = 0; j < Bsz; j++) {
        int e = (sl[j] == lab);
        c += e;
        r += e & (j < b);
    }
    g_rank[b] = r;
    g_cntb[b] = c;
}

// ---------------- ptr outputs --------------------------------------------
__global__ void ptr_k(const int* __restrict__ lk, const int* __restrict__ nptr,
                      const int* __restrict__ pptr, float* __restrict__ out)
{
    __shared__ int sl[Bsz];
    for (int i = threadIdx.x; i < Bsz; i += blockDim.x) sl[i] = lk[i];
    __syncthreads();
    int c = blockIdx.x * blockDim.x + threadIdx.x;
    int cnt = 0;
    for (int j = 0; j < Bsz; j++) cnt += (sl[j] == c);
    out[OFF_NPTR + c] = (float)((nptr[c] + cnt) % NNq);
    out[OFF_PPTR + c] = (float)((pptr[c] + cnt) % PP);
}

// ---------------- queue overwrite: survivors only ------------------------
__global__ void queue_update_k(const int* __restrict__ lk, const int* __restrict__ nptr,
                               const int* __restrict__ pptr, float* __restrict__ out)
{
    int b = blockIdx.x;
    int d = threadIdx.x;   // 128
    int lab = lk[b];
    int r = g_rank[b];
    int c = g_cntb[b];
    float v = g_featk[(size_t)b * DIM + d];
    if (r >= c - NNq) {
        int slot = (nptr[lab] + r) % NNq;
        out[OFF_NQ2 + (size_t)d * NC + lab * NNq + slot] = v;
    }
    if (r >= c - PP) {
        int slot = (pptr[lab] + r) % PP;
        out[OFF_PQ2 + (size_t)d * PC + lab * PP + slot] = v;
    }
}

// ---------------- host launcher -------------------------------------------
static float* symf(const void* sym) {
    void* p = nullptr;
    cudaGetSymbolAddress(&p, sym);
    return (float*)p;
}

extern "C" void kernel_launch(void* const* d_in, const int* in_sizes, int n_in,
                              void* d_out, int out_size)
{
    (void)in_sizes; (void)n_in; (void)out_size;
    const float* midq  = (const float*)d_in[0];
    const float* midk  = (const float*)d_in[1];
    const int*   lq    = (const int*)d_in[2];
    const int*   lk    = (const int*)d_in[3];
    const float* W1    = (const float*)d_in[4];
    const float* b1    = (const float*)d_in[5];
    const float* gamma = (const float*)d_in[6];
    const float* beta  = (const float*)d_in[7];
    const float* W2    = (const float*)d_in[8];
    const float* b2    = (const float*)d_in[9];
    const float* Wlin  = (const float*)d_in[10];
    const float* blin  = (const float*)d_in[11];
    const float* negq  = (const float*)d_in[12];
    const float* posq  = (const float*)d_in[13];
    const int*   nptr  = (const int*)d_in[14];
    const int*   pptr  = (const int*)d_in[15];
    float* out = (float*)d_out;

    float* Hq  = symf(g_Hq);
    float* Hk  = symf(g_Hk);
    float* scq = symf(g_scq); float* shq = symf(g_shq);
    float* sck = symf(g_sck); float* shk = symf(g_shk);
    float* fq  = symf(g_featq);
    float* fk  = symf(g_featk);
    float* fpart = symf(g_fpart);

    // copy queues to output (updates overwrite below)
    cudaMemcpyAsync(out + OFF_NQ2, negq, sizeof(float) * (size_t)DIM * NC,
                    cudaMemcpyDeviceToDevice);
    cudaMemcpyAsync(out + OFF_PQ2, posq, sizeof(float) * (size_t)DIM * PC,
                    cudaMemcpyDeviceToDevice);

    // logits: mid @ Wlin + blin (independent — big, launch early)
    tgemm_k<0><<<dim3(CC / 128, Bsz / 128, 2), 256>>>(
        midq, midk, Wlin, blin, out + OFF_LQ, out + OFF_LK,
        DF, DF, CC, CC, nullptr, nullptr, nullptr, nullptr, nullptr);

    // H = mid @ W1 + b1 (q and k batched via z)
    tgemm_k<0><<<dim3(DF / 128, Bsz / 128, 2), 256>>>(
        midq, midk, W1, b1, Hq, Hk,
        DF, DF, DF, DF, nullptr, nullptr, nullptr, nullptr, nullptr);

    // BN affine params (q and k batched via z)
    bn_stats_k<<<dim3(DF / 32, 1, 2), dim3(32, 32)>>>(
        Hq, Hk, gamma, beta, scq, shq, sck, shk);

    // feat partials = relu(BN(H)) @ W2 (split-K=16, q/k via z)
    tgemm_k<2><<<dim3(1, Bsz / 128, 2 * SPLITK), 256>>>(
        Hq, Hk, W2, nullptr, fpart, nullptr,
        DF, DF, DIM, DIM, scq, shq, sck, shk, nullptr);

    // reduce partials + bias + l2norm
    reduce_l2_k<<<dim3(Bsz, 2), DIM>>>(b2);

    // sim_batch = feat_q @ feat_k^T
    tgemm_k<3><<<dim3(Bsz / 128, Bsz / 128, 1), 256>>>(
        fq, nullptr, fk, nullptr, out + OFF_SIM, nullptr,
        DIM, DIM, DIM, SIMW, nullptr, nullptr, nullptr, nullptr, nullptr);

    // pos_list into sim_con[:, B:B+P]
    pos_k<<<Bsz, 256>>>(lq, posq, out);

    // neg gathered into sim_con[:, B+P:]
    tgemm_k<4><<<dim3(NC / 128, Bsz / 128, 1), 256>>>(
        fq, nullptr, negq, nullptr, out + OFF_SIM + Bsz + PP, nullptr,
        DIM, DIM, NC, SIMW, nullptr, nullptr, nullptr, nullptr, lq);

    // labels_con
    {
        size_t total4 = (size_t)Bsz * (SIMW / 4);
        int blocks = (int)((total4 + 255) / 256);
        labels_fill_k<<<blocks, 256>>>(lq, lk, out);
    }

    // queue update machinery
    rank_k<<<1, Bsz>>>(lk);
    ptr_k<<<CC / 256, 256>>>(lk, nptr, pptr, out);
    queue_update_k<<<Bsz, DIM>>>(lk, nptr, pptr, out);
}